// round 3
// baseline (speedup 1.0000x reference)
#include <cuda_runtime.h>
#include <cuda_bf16.h>
#include <cstdint>

// ============================================================================
// LPDecoder: out[e] = sigmoid( relu( [z[s]|z[d]] @ W1 + b1 ) @ W2 + b2 )
//
// Restructured:  UV = z @ [W1_top | W1_bot]   (one GEMM over nodes, tf32 MMA)
//                h  = relu(UV[s][0:128] + UV[d][128:256] + b1)
//                out = sigmoid(h . W2 + b2)
// FLOP drop: 65.8 GF (per-edge GEMM) -> 6.55 GF (per-node GEMM) + 0.4 GF edge.
//
// NOTE: edge_index is int32 (JAX default config downcasts int64 -> int32).
// ============================================================================

#define N_NODES_MAX 100000
#define SAP 132   // sA row stride (floats) - conflict-free A frag loads
#define SBP 136   // sB row stride (floats) - conflict-free B frag loads

static __device__ float g_UV[(size_t)N_NODES_MAX * 256];  // 102.4 MB scratch

__device__ __forceinline__ float to_tf32(float x) {
    uint32_t u;
    asm("cvt.rna.tf32.f32 %0, %1;" : "=r"(u) : "f"(x));
    return __uint_as_float(u);
}

// ----------------------------------------------------------------------------
// Kernel 1: UV[m][by*128 + n] = sum_k z[m][k] * W1[by*128 + k][n]
// Block: 256 threads (8 warps), tile M=256 x N=128 (grid.y = by in {0,1}), K=128.
// Warp (wr, wc): wr = warp>>2 owns 128 rows, wc = warp&3 owns 32 cols.
// tf32 mma.sync m16n8k8, accumulators fp32.
// ----------------------------------------------------------------------------
#define SMEM_FLOATS (256 * SAP + 128 * SBP)

__global__ void __launch_bounds__(256, 1)
gemm_uv(const float* __restrict__ z, const float* __restrict__ W1, int M)
{
    extern __shared__ float smem[];
    float* sA = smem;               // [256][SAP]
    float* sB = smem + 256 * SAP;   // [128][SBP]

    const int tid = threadIdx.x;
    const int m0  = blockIdx.x * 256;
    const int by  = blockIdx.y;           // 0: W1 rows 0..127, 1: rows 128..255

    // ---- Load A tile: z[m0 .. m0+255][0..127] -> tf32 in sA ----
    #pragma unroll
    for (int it = 0; it < 32; ++it) {
        int idx = tid + it * 256;         // float4 index, 8192 total
        int r   = idx >> 5;
        int c4  = (idx & 31) << 2;
        float4 v = make_float4(0.f, 0.f, 0.f, 0.f);
        if (m0 + r < M)
            v = *(const float4*)(z + (size_t)(m0 + r) * 128 + c4);
        float4 t = make_float4(to_tf32(v.x), to_tf32(v.y), to_tf32(v.z), to_tf32(v.w));
        *(float4*)(sA + r * SAP + c4) = t;
    }
    // ---- Load B tile: W1[by*128 + k][0..127] -> tf32 in sB ----
    const float* W1h = W1 + (size_t)by * 128 * 128;
    #pragma unroll
    for (int it = 0; it < 16; ++it) {
        int idx = tid + it * 256;         // 4096 float4s
        int r   = idx >> 5;
        int c4  = (idx & 31) << 2;
        float4 v = *(const float4*)(W1h + (size_t)r * 128 + c4);
        float4 t = make_float4(to_tf32(v.x), to_tf32(v.y), to_tf32(v.z), to_tf32(v.w));
        *(float4*)(sB + r * SBP + c4) = t;
    }
    __syncthreads();

    const int w    = tid >> 5;
    const int lane = tid & 31;
    const int g    = lane >> 2;   // groupID
    const int tig  = lane & 3;    // thread in group
    const int wr   = w >> 2;      // warp row (0/1): rows wr*128 ..
    const int wc   = w & 3;       // warp col: cols wc*32 ..
    const int n0w  = wc * 32;
    const int rbase = wr * 128;

    float c[8][4][4];
    #pragma unroll
    for (int mt = 0; mt < 8; ++mt)
        #pragma unroll
        for (int nt = 0; nt < 4; ++nt)
            #pragma unroll
            for (int i = 0; i < 4; ++i) c[mt][nt][i] = 0.f;

    #pragma unroll
    for (int kt = 0; kt < 16; ++kt) {
        uint32_t bf[4][2];
        #pragma unroll
        for (int nt = 0; nt < 4; ++nt) {
            int col = n0w + nt * 8 + g;
            bf[nt][0] = __float_as_uint(sB[(kt * 8 + tig) * SBP + col]);
            bf[nt][1] = __float_as_uint(sB[(kt * 8 + tig + 4) * SBP + col]);
        }
        #pragma unroll
        for (int mt = 0; mt < 8; ++mt) {
            int row = rbase + mt * 16 + g;
            int kc  = kt * 8 + tig;
            uint32_t a0 = __float_as_uint(sA[row * SAP + kc]);
            uint32_t a1 = __float_as_uint(sA[(row + 8) * SAP + kc]);
            uint32_t a2 = __float_as_uint(sA[row * SAP + kc + 4]);
            uint32_t a3 = __float_as_uint(sA[(row + 8) * SAP + kc + 4]);
            #pragma unroll
            for (int nt = 0; nt < 4; ++nt) {
                asm volatile(
                    "mma.sync.aligned.m16n8k8.row.col.f32.tf32.tf32.f32 "
                    "{%0,%1,%2,%3}, {%4,%5,%6,%7}, {%8,%9}, {%0,%1,%2,%3};"
                    : "+f"(c[mt][nt][0]), "+f"(c[mt][nt][1]),
                      "+f"(c[mt][nt][2]), "+f"(c[mt][nt][3])
                    : "r"(a0), "r"(a1), "r"(a2), "r"(a3),
                      "r"(bf[nt][0]), "r"(bf[nt][1]));
            }
        }
    }

    // ---- Epilogue: write UV (col offset by*128) ----
    #pragma unroll
    for (int mt = 0; mt < 8; ++mt) {
        int row0 = m0 + rbase + mt * 16 + g;
        int row1 = row0 + 8;
        #pragma unroll
        for (int nt = 0; nt < 4; ++nt) {
            int coln = by * 128 + n0w + nt * 8 + 2 * tig;
            if (row0 < M)
                *(float2*)(g_UV + (size_t)row0 * 256 + coln) =
                    make_float2(c[mt][nt][0], c[mt][nt][1]);
            if (row1 < M)
                *(float2*)(g_UV + (size_t)row1 * 256 + coln) =
                    make_float2(c[mt][nt][2], c[mt][nt][3]);
        }
    }
}

// ----------------------------------------------------------------------------
// Kernel 2: warp per edge. Lane l covers hidden dims 4l..4l+3.
//   h = relu(UV[s][j] + UV[d][128+j] + b1[j]);  logit = h.W2 + b2; sigmoid.
// edge_index is int32: ei[0..E) = src, ei[E..2E) = dst.
// ----------------------------------------------------------------------------
__global__ void __launch_bounds__(256)
edge_kernel(const int* __restrict__ ei,
            const float* __restrict__ b1,
            const float* __restrict__ W2,
            const float* __restrict__ b2,
            float* __restrict__ out, int E)
{
    const int lane   = threadIdx.x & 31;
    const int gwarp  = (blockIdx.x * blockDim.x + threadIdx.x) >> 5;
    const int nwarps = (gridDim.x * blockDim.x) >> 5;
    const int cbase  = lane * 4;

    const float4 w2 = *(const float4*)(W2 + cbase);
    const float4 bb = *(const float4*)(b1 + cbase);
    const float bias2 = b2[0];

    for (int e = gwarp; e < E; e += nwarps) {
        int s = ei[e];
        int d = ei[E + e];
        float4 u = *(const float4*)(g_UV + (size_t)s * 256 + cbase);
        float4 v = *(const float4*)(g_UV + (size_t)d * 256 + 128 + cbase);

        float p = fmaxf(u.x + v.x + bb.x, 0.f) * w2.x
                + fmaxf(u.y + v.y + bb.y, 0.f) * w2.y
                + fmaxf(u.z + v.z + bb.z, 0.f) * w2.z
                + fmaxf(u.w + v.w + bb.w, 0.f) * w2.w;

        #pragma unroll
        for (int off = 16; off > 0; off >>= 1)
            p += __shfl_xor_sync(0xffffffffu, p, off);

        if (lane == 0)
            out[e] = 1.0f / (1.0f + __expf(-(p + bias2)));
    }
}

// ----------------------------------------------------------------------------
extern "C" void kernel_launch(void* const* d_in, const int* in_sizes, int n_in,
                              void* d_out, int out_size)
{
    const float* z   = (const float*)d_in[0];
    const int*   ei  = (const int*)d_in[1];
    const float* W1  = (const float*)d_in[2];
    const float* b1  = (const float*)d_in[3];
    const float* W2  = (const float*)d_in[4];
    const float* b2  = (const float*)d_in[5];
    float*       out = (float*)d_out;

    int M = in_sizes[0] / 128;   // nodes
    int E = in_sizes[1] / 2;     // edges

    const int smem_bytes = SMEM_FLOATS * sizeof(float);  // 204,800 B
    cudaFuncSetAttribute(gemm_uv, cudaFuncAttributeMaxDynamicSharedMemorySize,
                         smem_bytes);

    dim3 grid1((M + 255) / 256, 2);
    gemm_uv<<<grid1, 256, smem_bytes>>>(z, W1, M);

    edge_kernel<<<1184, 256>>>(ei, b1, W2, b2, out, E);
}

// round 4
// speedup vs baseline: 1.1621x; 1.1621x over previous
#include <cuda_runtime.h>
#include <cuda_fp16.h>
#include <cstdint>

// ============================================================================
// LPDecoder: out[e] = sigmoid( relu( [z[s]|z[d]] @ W1 + b1 ) @ W2 + b2 )
//
// Restructured:  UV = z @ [W1_top | W1_bot]   (one GEMM over nodes, tf32 MMA)
//                h  = relu(UV[s][0:128] + UV[d][128:256] + b1)
//                out = sigmoid(h . W2 + b2)
//
// R4: UV stored as fp16 (same 10-bit mantissa as tf32 -> no precision loss
//     vs R3). 51.2 MB scratch fits in L2. GEMM fused over both W1 halves so
//     z is read once. Edge kernel 2-way unrolled for MLP.
// ============================================================================

#define N_NODES_MAX 100000
#define SAP 132   // sA row stride (floats) - conflict-free A frag loads
#define SBP 136   // sB row stride (floats) - conflict-free B frag loads

static __device__ __half g_UV[(size_t)N_NODES_MAX * 256];  // 51.2 MB scratch

__device__ __forceinline__ float to_tf32(float x) {
    uint32_t u;
    asm("cvt.rna.tf32.f32 %0, %1;" : "=r"(u) : "f"(x));
    return __uint_as_float(u);
}

// ----------------------------------------------------------------------------
// Kernel 1: UV[m][by*128 + n] = sum_k z[m][k] * W1[by*128 + k][n], by in {0,1}
// One block: 256 threads (8 warps), tile M=256 x N=128, K=128, loops by=0,1
// reusing the A tile. tf32 mma.sync m16n8k8, fp32 accum, fp16 store.
// ----------------------------------------------------------------------------
#define SMEM_FLOATS (256 * SAP + 128 * SBP)

__global__ void __launch_bounds__(256, 1)
gemm_uv(const float* __restrict__ z, const float* __restrict__ W1, int M)
{
    extern __shared__ float smem[];
    float* sA = smem;               // [256][SAP]
    float* sB = smem + 256 * SAP;   // [128][SBP]

    const int tid = threadIdx.x;
    const int m0  = blockIdx.x * 256;

    // ---- Load A tile once: z[m0 .. m0+255][0..127] -> tf32 in sA ----
    #pragma unroll
    for (int it = 0; it < 32; ++it) {
        int idx = tid + it * 256;         // float4 index, 8192 total
        int r   = idx >> 5;
        int c4  = (idx & 31) << 2;
        float4 v = make_float4(0.f, 0.f, 0.f, 0.f);
        if (m0 + r < M)
            v = *(const float4*)(z + (size_t)(m0 + r) * 128 + c4);
        float4 t = make_float4(to_tf32(v.x), to_tf32(v.y), to_tf32(v.z), to_tf32(v.w));
        *(float4*)(sA + r * SAP + c4) = t;
    }

    const int w    = tid >> 5;
    const int lane = tid & 31;
    const int g    = lane >> 2;   // groupID
    const int tig  = lane & 3;    // thread in group
    const int wr   = w >> 2;      // warp row (0/1): rows wr*128 ..
    const int wc   = w & 3;       // warp col: cols wc*32 ..
    const int n0w  = wc * 32;
    const int rbase = wr * 128;

    for (int by = 0; by < 2; ++by) {
        // ---- Load B tile: W1[by*128 + k][0..127] -> tf32 in sB ----
        __syncthreads();   // by=1: prior MMA reads of sB complete
        const float* W1h = W1 + (size_t)by * 128 * 128;
        #pragma unroll
        for (int it = 0; it < 16; ++it) {
            int idx = tid + it * 256;     // 4096 float4s
            int r   = idx >> 5;
            int c4  = (idx & 31) << 2;
            float4 v = *(const float4*)(W1h + (size_t)r * 128 + c4);
            float4 t = make_float4(to_tf32(v.x), to_tf32(v.y), to_tf32(v.z), to_tf32(v.w));
            *(float4*)(sB + r * SBP + c4) = t;
        }
        __syncthreads();

        float c[8][4][4];
        #pragma unroll
        for (int mt = 0; mt < 8; ++mt)
            #pragma unroll
            for (int nt = 0; nt < 4; ++nt)
                #pragma unroll
                for (int i = 0; i < 4; ++i) c[mt][nt][i] = 0.f;

        #pragma unroll
        for (int kt = 0; kt < 16; ++kt) {
            uint32_t bf[4][2];
            #pragma unroll
            for (int nt = 0; nt < 4; ++nt) {
                int col = n0w + nt * 8 + g;
                bf[nt][0] = __float_as_uint(sB[(kt * 8 + tig) * SBP + col]);
                bf[nt][1] = __float_as_uint(sB[(kt * 8 + tig + 4) * SBP + col]);
            }
            #pragma unroll
            for (int mt = 0; mt < 8; ++mt) {
                int row = rbase + mt * 16 + g;
                int kc  = kt * 8 + tig;
                uint32_t a0 = __float_as_uint(sA[row * SAP + kc]);
                uint32_t a1 = __float_as_uint(sA[(row + 8) * SAP + kc]);
                uint32_t a2 = __float_as_uint(sA[row * SAP + kc + 4]);
                uint32_t a3 = __float_as_uint(sA[(row + 8) * SAP + kc + 4]);
                #pragma unroll
                for (int nt = 0; nt < 4; ++nt) {
                    asm volatile(
                        "mma.sync.aligned.m16n8k8.row.col.f32.tf32.tf32.f32 "
                        "{%0,%1,%2,%3}, {%4,%5,%6,%7}, {%8,%9}, {%0,%1,%2,%3};"
                        : "+f"(c[mt][nt][0]), "+f"(c[mt][nt][1]),
                          "+f"(c[mt][nt][2]), "+f"(c[mt][nt][3])
                        : "r"(a0), "r"(a1), "r"(a2), "r"(a3),
                          "r"(bf[nt][0]), "r"(bf[nt][1]));
                }
            }
        }

        // ---- Epilogue: write UV half 'by' as fp16 ----
        #pragma unroll
        for (int mt = 0; mt < 8; ++mt) {
            int row0 = m0 + rbase + mt * 16 + g;
            int row1 = row0 + 8;
            #pragma unroll
            for (int nt = 0; nt < 4; ++nt) {
                int coln = by * 128 + n0w + nt * 8 + 2 * tig;
                if (row0 < M)
                    *(__half2*)(g_UV + (size_t)row0 * 256 + coln) =
                        __floats2half2_rn(c[mt][nt][0], c[mt][nt][1]);
                if (row1 < M)
                    *(__half2*)(g_UV + (size_t)row1 * 256 + coln) =
                        __floats2half2_rn(c[mt][nt][2], c[mt][nt][3]);
            }
        }
    }
}

// ----------------------------------------------------------------------------
// Kernel 2: warp per edge, 2 edges per iteration. Lane l covers dims 4l..4l+3.
//   h = relu(UV[s][j] + UV[d][128+j] + b1[j]);  logit = h.W2 + b2; sigmoid.
// edge_index is int32: ei[0..E) = src, ei[E..2E) = dst.
// ----------------------------------------------------------------------------
__device__ __forceinline__ float edge_partial(int s, int d, int cbase,
                                              float4 bb, float4 w2)
{
    uint2 ur = *(const uint2*)(g_UV + (size_t)s * 256 + cbase);
    uint2 vr = *(const uint2*)(g_UV + (size_t)d * 256 + 128 + cbase);
    float2 u0 = __half22float2(*(__half2*)&ur.x);
    float2 u1 = __half22float2(*(__half2*)&ur.y);
    float2 v0 = __half22float2(*(__half2*)&vr.x);
    float2 v1 = __half22float2(*(__half2*)&vr.y);
    return fmaxf(u0.x + v0.x + bb.x, 0.f) * w2.x
         + fmaxf(u0.y + v0.y + bb.y, 0.f) * w2.y
         + fmaxf(u1.x + v1.x + bb.z, 0.f) * w2.z
         + fmaxf(u1.y + v1.y + bb.w, 0.f) * w2.w;
}

__global__ void __launch_bounds__(256)
edge_kernel(const int* __restrict__ ei,
            const float* __restrict__ b1,
            const float* __restrict__ W2,
            const float* __restrict__ b2,
            float* __restrict__ out, int E)
{
    const int lane   = threadIdx.x & 31;
    const int gwarp  = (blockIdx.x * blockDim.x + threadIdx.x) >> 5;
    const int nwarps = (gridDim.x * blockDim.x) >> 5;
    const int cbase  = lane * 4;

    const float4 w2 = *(const float4*)(W2 + cbase);
    const float4 bb = *(const float4*)(b1 + cbase);
    const float bias2 = b2[0];

    for (int e0 = gwarp * 2; e0 < E; e0 += nwarps * 2) {
        int e1 = e0 + 1;
        int s0 = ei[e0];
        int d0 = ei[E + e0];
        float p0 = edge_partial(s0, d0, cbase, bb, w2);

        float p1 = 0.f;
        bool has1 = (e1 < E);
        if (has1) {
            int s1 = ei[e1];
            int d1 = ei[E + e1];
            p1 = edge_partial(s1, d1, cbase, bb, w2);
        }

        #pragma unroll
        for (int off = 16; off > 0; off >>= 1) {
            p0 += __shfl_xor_sync(0xffffffffu, p0, off);
            p1 += __shfl_xor_sync(0xffffffffu, p1, off);
        }

        if (lane == 0) {
            out[e0] = 1.0f / (1.0f + __expf(-(p0 + bias2)));
            if (has1)
                out[e1] = 1.0f / (1.0f + __expf(-(p1 + bias2)));
        }
    }
}

// ----------------------------------------------------------------------------
extern "C" void kernel_launch(void* const* d_in, const int* in_sizes, int n_in,
                              void* d_out, int out_size)
{
    const float* z   = (const float*)d_in[0];
    const int*   ei  = (const int*)d_in[1];
    const float* W1  = (const float*)d_in[2];
    const float* b1  = (const float*)d_in[3];
    const float* W2  = (const float*)d_in[4];
    const float* b2  = (const float*)d_in[5];
    float*       out = (float*)d_out;

    int M = in_sizes[0] / 128;   // nodes
    int E = in_sizes[1] / 2;     // edges

    const int smem_bytes = SMEM_FLOATS * sizeof(float);  // 204,800 B
    cudaFuncSetAttribute(gemm_uv, cudaFuncAttributeMaxDynamicSharedMemorySize,
                         smem_bytes);

    gemm_uv<<<(M + 255) / 256, 256, smem_bytes>>>(z, W1, M);

    edge_kernel<<<1184, 256>>>(ei, b1, W2, b2, out, E);
}

// round 6
// speedup vs baseline: 1.5760x; 1.3562x over previous
#include <cuda_runtime.h>
#include <cuda_fp16.h>
#include <cstdint>

// ============================================================================
// LPDecoder: out[e] = sigmoid( relu( [z[s]|z[d]] @ W1 + b1 ) @ W2 + b2 )
//
// UV = z @ [W1_top | W1_bot] + [b1 | 0]   (fp16 m16n8k16 MMA, fp32 accum)
// out[e] = sigmoid( relu(UV[s][0:128] + UV[d][128:256]) . W2 + b2 )
//
// R6: fp16 GEMM (same 10-bit mantissa as tf32; 2 blocks/SM), b1 folded into
//     UV, edge kernel uses half-warp-per-edge with uint4 loads + half2 math.
//     (R5 compile fix: store A tile through __half2*, no fake intrinsic.)
// ============================================================================

#define N_NODES_MAX 100000
#define SAP2 136            // sA row stride in halves (16B pad)

static __device__ __half g_UV[(size_t)N_NODES_MAX * 256];  // 51.2 MB scratch

// ----------------------------------------------------------------------------
// Kernel 1: UV[m][by*128+n] = sum_k z[m][k]*W1[by*128+k][n]  (+b1[n] for by=0)
// Block 256 thr (8 warps, 2x4), tile M=128 x N=128, K=128, by-loop reuses sA.
// sA: [128][SAP2] halves. sB: [n][k] halves, XOR-swizzled (k ^ ((n&7)<<3)).
// ----------------------------------------------------------------------------
#define SMEM_HALVES (128 * SAP2 + 128 * 128)

__global__ void __launch_bounds__(256, 2)
gemm_uv(const float* __restrict__ z, const float* __restrict__ W1,
        const float* __restrict__ b1, int M)
{
    extern __shared__ __half smemh[];
    __half* sA = smemh;                 // [128][SAP2]
    __half* sB = smemh + 128 * SAP2;    // [128 n][128 k], swizzled

    const int tid = threadIdx.x;
    const int m0  = blockIdx.x * 128;

    // ---- Load A tile: z[m0..m0+127][0..127] -> fp16 sA ----
    #pragma unroll
    for (int it = 0; it < 16; ++it) {
        int idx = tid + it * 256;        // float4 index, 4096 total
        int r   = idx >> 5;
        int c4  = (idx & 31) << 2;
        float4 v = make_float4(0.f, 0.f, 0.f, 0.f);
        if (m0 + r < M)
            v = *(const float4*)(z + (size_t)(m0 + r) * 128 + c4);
        __half2* dst = (__half2*)(sA + r * SAP2 + c4);
        dst[0] = __floats2half2_rn(v.x, v.y);
        dst[1] = __floats2half2_rn(v.z, v.w);
    }

    const int w     = tid >> 5;
    const int lane  = tid & 31;
    const int g     = lane >> 2;   // groupID 0..7
    const int tig   = lane & 3;    // 0..3
    const int wr    = w >> 2;      // 0/1 -> rows wr*64 ..
    const int wc    = w & 3;       // cols wc*32 ..
    const int n0w   = wc * 32;
    const int rbase = wr * 64;

    for (int by = 0; by < 2; ++by) {
        __syncthreads();             // by=1: prior MMA reads of sB done
        // ---- Load+transpose B: W1[by*128+k][n] -> sB[n][k^((n&7)<<3)] ----
        const float* W1h = W1 + (size_t)by * 128 * 128;
        #pragma unroll
        for (int it = 0; it < 64; ++it) {
            int idx = tid + it * 256;    // 16384 scalars
            int k   = idx >> 7;
            int n   = idx & 127;
            float v = W1h[k * 128 + n];  // coalesced along n
            sB[n * 128 + (k ^ ((n & 7) << 3))] = __float2half_rn(v);
        }
        __syncthreads();

        float c[4][4][4];
        #pragma unroll
        for (int mt = 0; mt < 4; ++mt)
            #pragma unroll
            for (int nt = 0; nt < 4; ++nt)
                #pragma unroll
                for (int i = 0; i < 4; ++i) c[mt][nt][i] = 0.f;

        #pragma unroll
        for (int kt = 0; kt < 8; ++kt) {
            const int ks = kt * 16 + 2 * tig;
            uint32_t bf[4][2];
            #pragma unroll
            for (int nt = 0; nt < 4; ++nt) {
                int n  = n0w + nt * 8 + g;        // n&7 == g
                int kx0 = ks ^ (g << 3);
                int kx1 = (ks + 8) ^ (g << 3);
                bf[nt][0] = *(const uint32_t*)(sB + n * 128 + kx0);
                bf[nt][1] = *(const uint32_t*)(sB + n * 128 + kx1);
            }
            #pragma unroll
            for (int mt = 0; mt < 4; ++mt) {
                int row = rbase + mt * 16 + g;
                uint32_t a0 = *(const uint32_t*)(sA + row * SAP2 + ks);
                uint32_t a1 = *(const uint32_t*)(sA + (row + 8) * SAP2 + ks);
                uint32_t a2 = *(const uint32_t*)(sA + row * SAP2 + ks + 8);
                uint32_t a3 = *(const uint32_t*)(sA + (row + 8) * SAP2 + ks + 8);
                #pragma unroll
                for (int nt = 0; nt < 4; ++nt) {
                    asm volatile(
                        "mma.sync.aligned.m16n8k16.row.col.f32.f16.f16.f32 "
                        "{%0,%1,%2,%3}, {%4,%5,%6,%7}, {%8,%9}, {%0,%1,%2,%3};"
                        : "+f"(c[mt][nt][0]), "+f"(c[mt][nt][1]),
                          "+f"(c[mt][nt][2]), "+f"(c[mt][nt][3])
                        : "r"(a0), "r"(a1), "r"(a2), "r"(a3),
                          "r"(bf[nt][0]), "r"(bf[nt][1]));
                }
            }
        }

        // ---- Epilogue: (+b1 if by==0), write fp16 UV ----
        #pragma unroll
        for (int mt = 0; mt < 4; ++mt) {
            int row0 = m0 + rbase + mt * 16 + g;
            int row1 = row0 + 8;
            #pragma unroll
            for (int nt = 0; nt < 4; ++nt) {
                int coln = n0w + nt * 8 + 2 * tig;
                float bx = 0.f, byv = 0.f;
                if (by == 0) {
                    float2 bb = *(const float2*)(b1 + coln);
                    bx = bb.x; byv = bb.y;
                }
                int colg = by * 128 + coln;
                if (row0 < M)
                    *(__half2*)(g_UV + (size_t)row0 * 256 + colg) =
                        __floats2half2_rn(c[mt][nt][0] + bx, c[mt][nt][1] + byv);
                if (row1 < M)
                    *(__half2*)(g_UV + (size_t)row1 * 256 + colg) =
                        __floats2half2_rn(c[mt][nt][2] + bx, c[mt][nt][3] + byv);
            }
        }
    }
}

// ----------------------------------------------------------------------------
// Kernel 2: half-warp per edge, 2 edges per half-warp per iteration.
// Lane covers 8 dims (uint4 = 8 halves). b1 already folded into UV.
//   h = relu(UV[s][j] + UV[d][128+j]);  out = sigmoid(h.W2 + b2)
// ----------------------------------------------------------------------------
__device__ __forceinline__ float edge_partial_h(int s, int d, int cb,
                                                float4 w2a, float4 w2b)
{
    uint4 ur = *(const uint4*)(g_UV + (size_t)s * 256 + cb);
    uint4 vr = *(const uint4*)(g_UV + (size_t)d * 256 + 128 + cb);
    const __half2 z2 = __half2half2(__ushort_as_half(0));

    __half2 h0 = __hmax2(__hadd2(*(__half2*)&ur.x, *(__half2*)&vr.x), z2);
    __half2 h1 = __hmax2(__hadd2(*(__half2*)&ur.y, *(__half2*)&vr.y), z2);
    __half2 h2 = __hmax2(__hadd2(*(__half2*)&ur.z, *(__half2*)&vr.z), z2);
    __half2 h3 = __hmax2(__hadd2(*(__half2*)&ur.w, *(__half2*)&vr.w), z2);

    float2 f0 = __half22float2(h0);
    float2 f1 = __half22float2(h1);
    float2 f2 = __half22float2(h2);
    float2 f3 = __half22float2(h3);

    return f0.x * w2a.x + f0.y * w2a.y + f1.x * w2a.z + f1.y * w2a.w
         + f2.x * w2b.x + f2.y * w2b.y + f3.x * w2b.z + f3.y * w2b.w;
}

__global__ void __launch_bounds__(256)
edge_kernel(const int* __restrict__ ei,
            const float* __restrict__ W2,
            const float* __restrict__ b2,
            float* __restrict__ out, int E)
{
    const int lane = threadIdx.x & 31;
    const int hw   = lane >> 4;          // half-warp id 0/1
    const int hl   = lane & 15;
    const int cb   = hl * 8;             // 8 halves per lane

    const int gwarp  = (blockIdx.x * blockDim.x + threadIdx.x) >> 5;
    const int nwarps = (gridDim.x * blockDim.x) >> 5;

    const float4 w2a = *(const float4*)(W2 + cb);
    const float4 w2b = *(const float4*)(W2 + cb + 4);
    const float bias2 = b2[0];

    for (int e0 = gwarp * 4; e0 < E; e0 += nwarps * 4) {
        int eA = e0 + hw;            // edges e0, e0+1 across the two halves
        int eB = e0 + 2 + hw;        // edges e0+2, e0+3
        bool vA = eA < E;
        bool vB = eB < E;

        int sA = vA ? ei[eA] : 0;
        int dA = vA ? ei[E + eA] : 0;
        int sB = vB ? ei[eB] : 0;
        int dB = vB ? ei[E + eB] : 0;

        float pA = edge_partial_h(sA, dA, cb, w2a, w2b);
        float pB = edge_partial_h(sB, dB, cb, w2a, w2b);

        #pragma unroll
        for (int off = 8; off > 0; off >>= 1) {
            pA += __shfl_xor_sync(0xffffffffu, pA, off);
            pB += __shfl_xor_sync(0xffffffffu, pB, off);
        }

        if (hl == 0) {
            if (vA) out[eA] = 1.0f / (1.0f + __expf(-(pA + bias2)));
            if (vB) out[eB] = 1.0f / (1.0f + __expf(-(pB + bias2)));
        }
    }
}

// ----------------------------------------------------------------------------
extern "C" void kernel_launch(void* const* d_in, const int* in_sizes, int n_in,
                              void* d_out, int out_size)
{
    const float* z   = (const float*)d_in[0];
    const int*   ei  = (const int*)d_in[1];
    const float* W1  = (const float*)d_in[2];
    const float* b1  = (const float*)d_in[3];
    const float* W2  = (const float*)d_in[4];
    const float* b2  = (const float*)d_in[5];
    float*       out = (float*)d_out;

    int M = in_sizes[0] / 128;   // nodes
    int E = in_sizes[1] / 2;     // edges

    const int smem_bytes = SMEM_HALVES * sizeof(__half);  // 67,584 B
    cudaFuncSetAttribute(gemm_uv, cudaFuncAttributeMaxDynamicSharedMemorySize,
                         smem_bytes);

    gemm_uv<<<(M + 127) / 128, 256, smem_bytes>>>(z, W1, b1, M);

    edge_kernel<<<1184, 256>>>(ei, W2, b2, out, E);
}